// round 14
// baseline (speedup 1.0000x reference)
#include <cuda_runtime.h>
#include <cuda_bf16.h>
#include <math.h>
#include <stdint.h>

#define TT 64
#define BB 32
#define SS 64
#define HH 1024
#define NBLK 128

typedef __nv_bfloat16 bf16;

// ---------------- static device scratch (no allocations) ----------------
__device__ uint32_t g_w0[(size_t)256 * 192 * 2 * 128];  // gates0: ks 0-63 ih0-emb, 64-127 ih0-feed, 128-191 hh0
__device__ uint32_t g_w1[(size_t)256 * 128 * 2 * 128];  // gates1: ks 0-63 ih1, 64-127 hh1
__device__ uint32_t g_wq[(size_t)64 * 64 * 2 * 128];    // q: W_in
__device__ uint32_t g_wo[(size_t)64 * 128 * 2 * 128];   // out: W_out (ks 0-63 cvec, 64-127 h1)

__device__ uint32_t g_embx[(size_t)TT * 32768];
__device__ uint32_t g_h0x[2][32768];   // double-buffered
__device__ uint32_t g_h1x[2][32768];
__device__ uint32_t g_feedx[32768];
__device__ uint32_t g_cvx[32768];

__device__ float g_ge[(size_t)TT * 4096 * 32];   // precomputed W_ih0_emb @ emb_t (permuted rows)
__device__ float g_c0T[HH * BB];
__device__ float g_c1T[HH * BB];
__device__ float g_qf[HH * BB];       // [b][row]

// epoch flags (32B-padded per block; monotonic epochs, no resets needed mid-run)
__device__ unsigned g_barA[128 * 8];
__device__ unsigned g_barB[128 * 8];
__device__ unsigned g_flagQ[64 * 8];
__device__ unsigned g_flagCV[32 * 8];
__device__ unsigned g_flagF[64 * 8];

// ---------------- helpers ----------------
__device__ __forceinline__ float sigm(float x) { return 1.f / (1.f + expf(-x)); }

__device__ __forceinline__ void store_x(bf16* base, int hh, int b, float v) {
    int kstep = hh >> 4, kk = hh & 15;
    int ntile = b >> 3, gid = b & 7;
    int reg = kk >> 3, krem = kk & 7, tig = krem >> 1, half = krem & 1;
    int lane = gid * 4 + tig;
    bf16 hi = __float2bfloat16(v);
    bf16 lo = __float2bfloat16(v - __bfloat162float(hi));
    size_t i0 = ((((size_t)kstep * 2 + 0) * 4 + ntile) * 64 + lane * 2 + reg) * 2 + half;
    size_t i1 = ((((size_t)kstep * 2 + 1) * 4 + ntile) * 64 + lane * 2 + reg) * 2 + half;
    base[i0] = hi;
    base[i1] = lo;
}

__device__ __forceinline__ void mma_bf16(float* d, const uint32_t* a, uint32_t b0, uint32_t b1) {
    asm volatile(
        "mma.sync.aligned.m16n8k16.row.col.f32.bf16.bf16.f32 "
        "{%0,%1,%2,%3}, {%4,%5,%6,%7}, {%8,%9}, {%0,%1,%2,%3};"
        : "+f"(d[0]), "+f"(d[1]), "+f"(d[2]), "+f"(d[3])
        : "r"(a[0]), "r"(a[1]), "r"(a[2]), "r"(a[3]), "r"(b0), "r"(b1));
}

// ---- epoch barriers: arrive = 1 uncontended atomic; wait = parallel polls ----
__device__ __forceinline__ void epoch_arrive(unsigned* flags, int slot, unsigned e) {
    __syncthreads();
    __threadfence();
    if (threadIdx.x == 0) atomicExch(&flags[slot * 8], e);
}
__device__ __forceinline__ void epoch_wait(unsigned* flags, int n, unsigned e) {
    if ((int)threadIdx.x < n)
        while (__ldcg(&flags[threadIdx.x * 8]) < e) __nanosleep(32);
    __syncthreads();
    __threadfence();
}
// warp-scope wait for all 64 feed flags (each lane polls 2)
__device__ __forceinline__ void warp_wait_feed(unsigned e, int lane) {
    while (__ldcg(&g_flagF[lane * 8]) < e || __ldcg(&g_flagF[(lane + 32) * 8]) < e)
        __nanosleep(32);
    __syncwarp();
    __threadfence();
}

// 2-rowtile warp GEMM: B loaded once per kstep, used for rt0 and rt0+1.
__device__ __forceinline__ void warp_gemm2(
    const uint32_t* __restrict__ Wt, int nk, int rt0, int k0, int kn, int split,
    const uint32_t* __restrict__ xlo, const uint32_t* __restrict__ xhi,
    float acc[2][4][4], int lane)
{
    const uint4* A0 = (const uint4*)(Wt + (((size_t)rt0 * nk + k0) * 2) * 128) + lane;
    const uint4* A1 = A0 + (size_t)nk * 64;
    #pragma unroll 4
    for (int s = 0; s < kn; s++) {
        int ks = k0 + s;
        const uint32_t* xs = (ks < split) ? xlo : xhi;
        const uint2* xb = (const uint2*)(xs + (size_t)(ks & 63) * 512);
        uint2 bh[4], bl[4];
        #pragma unroll
        for (int nt = 0; nt < 4; nt++) {
            bh[nt] = __ldcg(&xb[nt * 32 + lane]);
            bl[nt] = __ldcg(&xb[128 + nt * 32 + lane]);
        }
        uint4 ah0 = __ldg(A0), al0 = __ldg(A0 + 32);
        uint4 ah1 = __ldg(A1), al1 = __ldg(A1 + 32);
        A0 += 64; A1 += 64;
        #pragma unroll
        for (int nt = 0; nt < 4; nt++) {
            mma_bf16(acc[0][nt], (const uint32_t*)&ah0, bh[nt].x, bh[nt].y);
            mma_bf16(acc[0][nt], (const uint32_t*)&ah0, bl[nt].x, bl[nt].y);
            mma_bf16(acc[0][nt], (const uint32_t*)&al0, bh[nt].x, bh[nt].y);
            mma_bf16(acc[1][nt], (const uint32_t*)&ah1, bh[nt].x, bh[nt].y);
            mma_bf16(acc[1][nt], (const uint32_t*)&ah1, bl[nt].x, bl[nt].y);
            mma_bf16(acc[1][nt], (const uint32_t*)&al1, bh[nt].x, bh[nt].y);
        }
    }
}

// 1-rowtile warp GEMM (q / out)
__device__ __forceinline__ void warp_gemm1(
    const uint32_t* __restrict__ Wt, int nk, int rt, int k0, int kn,
    const uint32_t* __restrict__ xlo, const uint32_t* __restrict__ xhi,
    float acc[4][4], int lane)
{
    const uint4* Ap = (const uint4*)(Wt + (((size_t)rt * nk + k0) * 2) * 128) + lane;
    #pragma unroll 4
    for (int s = 0; s < kn; s++) {
        int ks = k0 + s;
        const uint32_t* xs = (ks < 64) ? xlo : xhi;
        const uint2* xb = (const uint2*)(xs + (size_t)(ks & 63) * 512);
        uint2 bh[4], bl[4];
        #pragma unroll
        for (int nt = 0; nt < 4; nt++) {
            bh[nt] = __ldcg(&xb[nt * 32 + lane]);
            bl[nt] = __ldcg(&xb[128 + nt * 32 + lane]);
        }
        uint4 ah = __ldg(Ap), al = __ldg(Ap + 32);
        Ap += 64;
        #pragma unroll
        for (int nt = 0; nt < 4; nt++) {
            mma_bf16(acc[nt], (const uint32_t*)&ah, bh[nt].x, bh[nt].y);
            mma_bf16(acc[nt], (const uint32_t*)&ah, bl[nt].x, bl[nt].y);
            mma_bf16(acc[nt], (const uint32_t*)&al, bh[nt].x, bh[nt].y);
        }
    }
}

__device__ __forceinline__ void acc_to_red(float* red, const float acc[4][4], int lane) {
    int gid = lane >> 2, tig = lane & 3;
    #pragma unroll
    for (int nt = 0; nt < 4; nt++) {
        int c = nt * 8 + tig * 2;
        red[gid * 32 + c]           = acc[nt][0];
        red[gid * 32 + c + 1]       = acc[nt][1];
        red[(gid + 8) * 32 + c]     = acc[nt][2];
        red[(gid + 8) * 32 + c + 1] = acc[nt][3];
    }
}

__device__ __forceinline__ void cell_tail(const float (*red)[2][512],
                                          const float* __restrict__ bih,
                                          const float* __restrict__ bhh,
                                          float* __restrict__ cT, uint32_t* __restrict__ hx,
                                          const float* __restrict__ ge,
                                          int bid, int tid)
{
    int hl = tid >> 5, bb = tid & 31;
    float gv[4];
    #pragma unroll
    for (int gt = 0; gt < 4; gt++) {
        int pib = gt * 8 + hl;
        int par = pib >> 4;
        int idx = (pib & 15) * 32 + bb;
        float s = 0.f;
        #pragma unroll
        for (int kc = 0; kc < 8; kc++) s += red[kc][par][idx];
        if (ge) s += __ldg(&ge[(size_t)(bid * 32 + pib) * 32 + bb]);
        gv[gt] = s;
    }
    int hh = bid * 8 + hl;
    float gi = gv[0] + bih[hh]            + bhh[hh];
    float gf = gv[1] + bih[1024 + hh]     + bhh[1024 + hh];
    float gg = gv[2] + bih[2048 + hh]     + bhh[2048 + hh];
    float go = gv[3] + bih[3072 + hh]     + bhh[3072 + hh];
    int e = hh * 32 + bb;
    float cn = sigm(gf) * cT[e] + sigm(gi) * tanhf(gg);
    cT[e] = cn;
    store_x((bf16*)hx, hh, bb, sigm(go) * tanhf(cn));
}

// ---------------- persistent sequence kernel ----------------
__global__ void __launch_bounds__(256, 1)
k_seq(const float* __restrict__ ctx, const int* __restrict__ lens,
      const float* __restrict__ bih0, const float* __restrict__ bhh0,
      const float* __restrict__ bih1, const float* __restrict__ bhh1,
      float* __restrict__ outv, float* __restrict__ attnout)
{
    __shared__ float red[8][2][512];
    __shared__ float sc[SS];
    int tid = threadIdx.x, w = tid >> 5, lane = tid & 31;
    int bid = blockIdx.x;

    for (int t = 0; t < TT; t++) {
        unsigned ep = (unsigned)t + 1u;
        int p = t & 1;
        const uint32_t* h0o = g_h0x[p];
        uint32_t*       h0n = g_h0x[p ^ 1];
        const uint32_t* h1o = g_h1x[p];
        uint32_t*       h1n = g_h1x[p ^ 1];

        // ---- P1: h0-half first (ready since last step), then feed-half after flagF ----
        {
            float acc[2][4][4] = {};
            warp_gemm2(g_w0, 192, bid * 2, 128 + w * 8, 8, 128, g_feedx, h0o, acc, lane);
            warp_wait_feed((unsigned)t, lane);   // feed from step t-1 (t=0 passes: flags=0)
            warp_gemm2(g_w0, 192, bid * 2, 64 + w * 8, 8, 128, g_feedx, h0o, acc, lane);
            acc_to_red(red[w][0], acc[0], lane);
            acc_to_red(red[w][1], acc[1], lane);
            __syncthreads();
            cell_tail(red, bih0, bhh0, g_c0T, h0n, g_ge + (size_t)t * 4096 * 32, bid, tid);
        }
        epoch_arrive(g_barA, bid, ep);
        epoch_wait(g_barA, 128, ep);

        // ---- P2: gates1 (h0n ks0-63, h1o ks64-127) + cell1 ----
        {
            float acc[2][4][4] = {};
            warp_gemm2(g_w1, 128, bid * 2, w * 16, 16, 64, h0n, h1o, acc, lane);
            acc_to_red(red[w][0], acc[0], lane);
            acc_to_red(red[w][1], acc[1], lane);
            __syncthreads();
            cell_tail(red, bih1, bhh1, g_c1T, h1n, nullptr, bid, tid);
        }
        epoch_arrive(g_barB, bid, ep);
        epoch_wait(g_barB, 128, ep);

        // ---- P3/P4/P5 (no trailing full barrier; flagF closes the loop) ----
        if (bid < 64) {
            float acc[4][4] = {};
            warp_gemm1(g_wq, 64, bid, w * 8, 8, h1n, h1n, acc, lane);
            acc_to_red(red[w][0], acc, lane);
            __syncthreads();
            #pragma unroll
            for (int j = 0; j < 2; j++) {
                int i = tid + j * 256;
                float s = 0.f;
                #pragma unroll
                for (int ww = 0; ww < 8; ww++) s += red[ww][0][i];
                int row = bid * 16 + (i >> 5), bb = i & 31;
                g_qf[(size_t)bb * HH + row] = s;
            }
            epoch_arrive(g_flagQ, bid, ep);

            if (bid >= 32) {
                epoch_wait(g_flagQ, 64, ep);
                int b = bid - 32;
                float* qs = &red[0][0][0];
                for (int i = tid; i < HH; i += 256)
                    qs[i] = __ldcg(&g_qf[(size_t)b * HH + i]);
                __syncthreads();

                #pragma unroll
                for (int si = 0; si < 8; si++) {
                    int s = w * 8 + si;
                    const float* cr = ctx + ((size_t)s * BB + b) * HH;
                    float sum = 0.f;
                    for (int i = lane; i < HH; i += 32) sum = fmaf(qs[i], __ldg(&cr[i]), sum);
                    #pragma unroll
                    for (int o = 16; o > 0; o >>= 1) sum += __shfl_xor_sync(0xffffffffu, sum, o);
                    if (lane == 0) sc[s] = sum;
                }
                __syncthreads();

                if (tid == 0) {
                    int len = lens[b];
                    len = len < 1 ? 1 : (len > SS ? SS : len);
                    float m = sc[0];
                    for (int s = 1; s < len; s++) m = fmaxf(m, sc[s]);
                    float sum = 0.f;
                    for (int s = 0; s < len; s++) { float e = expf(sc[s] - m); sc[s] = e; sum += e; }
                    float inv = 1.f / sum;
                    for (int s = 0; s < len; s++) sc[s] *= inv;
                    for (int s = len; s < SS; s++) sc[s] = 0.f;
                }
                __syncthreads();

                if (tid < SS) attnout[((size_t)t * BB + b) * SS + tid] = sc[tid];

                #pragma unroll
                for (int j = 0; j < 4; j++) {
                    int hh = tid + j * 256;
                    float a = 0.f;
                    for (int s = 0; s < SS; s++)
                        a = fmaf(sc[s], __ldg(&ctx[((size_t)s * BB + b) * HH + hh]), a);
                    store_x((bf16*)g_cvx, hh, b, a);
                }
                epoch_arrive(g_flagCV, bid - 32, ep);
            }
        } else {
            int rt = bid - 64;
            float acc[4][4] = {};
            warp_gemm1(g_wo, 128, rt, 64 + w * 8, 8, g_cvx, h1n, acc, lane);  // h1 half
            epoch_wait(g_flagCV, 32, ep);
            warp_gemm1(g_wo, 128, rt, w * 8, 8, g_cvx, h1n, acc, lane);       // cvec half
            acc_to_red(red[w][0], acc, lane);
            __syncthreads();
            #pragma unroll
            for (int j = 0; j < 2; j++) {
                int i = tid + j * 256;
                float v = 0.f;
                #pragma unroll
                for (int ww = 0; ww < 8; ww++) v += red[ww][0][i];
                int hh = rt * 16 + (i >> 5), bb = i & 31;
                v = tanhf(v);
                outv[((size_t)t * BB + bb) * HH + hh] = v;
                store_x((bf16*)g_feedx, hh, bb, v);
            }
            epoch_arrive(g_flagF, rt, ep);
        }
    }
}

// ---------------- prologue: gates0 emb contribution for ALL t ----------------
__global__ void __launch_bounds__(256, 1)
k_embgemm() {
    __shared__ uint32_t stage[4][512];
    int tid = threadIdx.x, w = tid >> 5, lane = tid & 31;
    int Mb = blockIdx.x, tg = blockIdx.y;
    int rt = Mb * 8 + w;

    float acc[4][4][4] = {};
    const uint4* Ap = (const uint4*)(g_w0 + (((size_t)rt * 192) * 2) * 128) + lane;

    for (int ks = 0; ks < 64; ks++) {
        __syncthreads();
        #pragma unroll
        for (int j = 0; j < 8; j++) {
            int u = tid + j * 256;
            stage[u >> 9][u & 511] =
                __ldg(&g_embx[(size_t)(tg * 4 + (u >> 9)) * 32768 + (size_t)ks * 512 + (u & 511)]);
        }
        __syncthreads();
        uint4 ah = __ldg(Ap), al = __ldg(Ap + 32);
        Ap += 64;
        #pragma unroll
        for (int tt = 0; tt < 4; tt++) {
            const uint2* xb = (const uint2*)stage[tt];
            #pragma unroll
            for (int nt = 0; nt < 4; nt++) {
                uint2 bh = xb[nt * 32 + lane];
                uint2 bl = xb[128 + nt * 32 + lane];
                mma_bf16(acc[tt][nt], (const uint32_t*)&ah, bh.x, bh.y);
                mma_bf16(acc[tt][nt], (const uint32_t*)&ah, bl.x, bl.y);
                mma_bf16(acc[tt][nt], (const uint32_t*)&al, bh.x, bh.y);
            }
        }
    }

    int gid = lane >> 2, tig = lane & 3;
    #pragma unroll
    for (int tt = 0; tt < 4; tt++) {
        float* gp = g_ge + ((size_t)(tg * 4 + tt) * 4096) * 32;
        #pragma unroll
        for (int nt = 0; nt < 4; nt++) {
            int row0 = rt * 16 + gid, col = nt * 8 + tig * 2;
            *(float2*)&gp[(size_t)row0 * 32 + col] = make_float2(acc[tt][nt][0], acc[tt][nt][1]);
            *(float2*)&gp[(size_t)(row0 + 8) * 32 + col] = make_float2(acc[tt][nt][2], acc[tt][nt][3]);
        }
    }
}

// ---------------- weight conversion (device fn + 2 merged launches) ----------------
__device__ __forceinline__ void wconv_one(const float* __restrict__ W, int ldw,
                                          uint32_t* __restrict__ dst, int nkTot, int ksBase,
                                          int gatePerm, int rt, int ks) {
    int lane = threadIdx.x;
    int gid = lane >> 2, tig = lane & 3;
    uint32_t hi[4], lo[4];
    #pragma unroll
    for (int r = 0; r < 4; r++) {
        int i = gid + (r & 1) * 8;
        int row;
        if (gatePerm) {
            int pib = (rt & 1) * 16 + i;
            int gate = pib >> 3, hho = pib & 7;
            row = gate * 1024 + (rt >> 1) * 8 + hho;
        } else {
            row = rt * 16 + i;
        }
        int kk = ks * 16 + (r >> 1) * 8 + tig * 2;
        float w0 = __ldg(&W[(size_t)row * ldw + kk]);
        float w1 = __ldg(&W[(size_t)row * ldw + kk + 1]);
        bf16 h0 = __float2bfloat16(w0), h1 = __float2bfloat16(w1);
        bf16 l0 = __float2bfloat16(w0 - __bfloat162float(h0));
        bf16 l1 = __float2bfloat16(w1 - __bfloat162float(h1));
        hi[r] = ((uint32_t)__bfloat16_as_ushort(h1) << 16) | __bfloat16_as_ushort(h0);
        lo[r] = ((uint32_t)__bfloat16_as_ushort(l1) << 16) | __bfloat16_as_ushort(l0);
    }
    size_t bi = (((size_t)rt * nkTot + ksBase + ks) * 2) * 128 + lane * 4;
    #pragma unroll
    for (int r = 0; r < 4; r++) {
        dst[bi + r] = hi[r];
        dst[bi + 128 + r] = lo[r];
    }
}

__global__ void k_wconvA(const float* ih0, const float* hh0, const float* ih1, const float* hh1) {
    int rt = blockIdx.x, ks = blockIdx.y, z = blockIdx.z;
    if (z == 0)      { wconv_one(ih0, 2048, g_w0, 192, 0,   1, rt, ks); }           // ks < 128
    else if (z == 1) { if (ks < 64) wconv_one(hh0, 1024, g_w0, 192, 128, 1, rt, ks); }
    else if (z == 2) { if (ks < 64) wconv_one(ih1, 1024, g_w1, 128, 0,   1, rt, ks); }
    else             { if (ks < 64) wconv_one(hh1, 1024, g_w1, 128, 64,  1, rt, ks); }
}
__global__ void k_wconvB(const float* win, const float* wout) {
    int rt = blockIdx.x, ks = blockIdx.y, z = blockIdx.z;
    if (z == 0) { if (ks < 64) wconv_one(win, 1024, g_wq, 64, 0, 0, rt, ks); }
    else        { wconv_one(wout, 2048, g_wo, 128, 0, 0, rt, ks); }                  // ks < 128
}

// ---------------- embedding gather ----------------
__global__ void k_embx(const int* __restrict__ ids, const float* __restrict__ emb) {
    int t = blockIdx.x;
    int tid = threadIdx.x;
    int b = tid & 31;
    int id = ids[t * BB + b];
    bf16* dstx = (bf16*)(g_embx + (size_t)t * 32768);
    const float* src = emb + (size_t)id * HH;
    for (int hh = tid >> 5; hh < HH; hh += 8)
        store_x(dstx, hh, b, __ldg(&src[hh]));
}

// ---------------- init: states + flag reset ----------------
__global__ void k_init(const float* __restrict__ h0, const float* __restrict__ c0) {
    int idx = blockIdx.x * 256 + threadIdx.x;
    if (idx < 128 * 8) { g_barA[idx] = 0u; g_barB[idx] = 0u; }
    if (idx < 64 * 8)  { g_flagQ[idx] = 0u; g_flagF[idx] = 0u; }
    if (idx < 32 * 8)  { g_flagCV[idx] = 0u; }
    if (idx >= HH * BB) return;
    int hh = idx >> 5, b = idx & 31;
    g_c0T[idx] = c0[(size_t)(0 * BB + b) * HH + hh];
    g_c1T[idx] = c0[(size_t)(1 * BB + b) * HH + hh];
    store_x((bf16*)g_h0x[0], hh, b, h0[(size_t)(0 * BB + b) * HH + hh]);
    store_x((bf16*)g_h1x[0], hh, b, h0[(size_t)(1 * BB + b) * HH + hh]);
    store_x((bf16*)g_feedx, hh, b, 0.f);
}

// ---------------- launcher (graph-capturable: kernel launches only) ----------------
extern "C" void kernel_launch(void* const* d_in, const int* in_sizes, int n_in,
                              void* d_out, int out_size) {
    const int*   ids   = (const int*)  d_in[0];
    const float* ctx   = (const float*)d_in[1];
    const int*   lens  = (const int*)  d_in[2];
    const float* h0    = (const float*)d_in[3];
    const float* c0    = (const float*)d_in[4];
    const float* emb   = (const float*)d_in[5];
    const float* W_ih0 = (const float*)d_in[6];
    const float* W_hh0 = (const float*)d_in[7];
    const float* b_ih0 = (const float*)d_in[8];
    const float* b_hh0 = (const float*)d_in[9];
    const float* W_ih1 = (const float*)d_in[10];
    const float* W_hh1 = (const float*)d_in[11];
    const float* b_ih1 = (const float*)d_in[12];
    const float* b_hh1 = (const float*)d_in[13];
    const float* W_in  = (const float*)d_in[14];
    const float* W_out = (const float*)d_in[15];

    float* outv = (float*)d_out;                      // outputs [T,B,H]
    float* attn = outv + (size_t)TT * BB * HH;        // attns   [T,B,S]

    // 5 setup launches, then k_seq is launch #6 (ncu -s 5 -c 1 captures it)
    k_wconvA<<<dim3(256, 128, 4), 32>>>(W_ih0, W_hh0, W_ih1, W_hh1);
    k_wconvB<<<dim3(64, 128, 2), 32>>>(W_in, W_out);
    k_embx<<<TT, 256>>>(ids, emb);
    k_init<<<128, 256>>>(h0, c0);
    k_embgemm<<<dim3(32, 16), 256>>>();

    k_seq<<<NBLK, 256>>>(ctx, lens, b_ih0, b_hh0, b_ih1, b_hh1, outv, attn);
}